// round 9
// baseline (speedup 1.0000x reference)
#include <cuda_runtime.h>

#define N_NODES  100000
#define F_IN     256
#define F_HID    64
#define F_OUT    40
#define EDGE_MAX 1700000

// Scratch (static device globals — no allocation allowed)
__device__ float  g_dis[N_NODES];             // rsqrt(weighted deg + 1)
__device__ float  g_deg[N_NODES];             // weighted degree accumulator
__device__ int    g_cnt[N_NODES];             // edges per destination
__device__ int    g_excl[N_NODES];            // local exclusive scan
__device__ int    g_bsum[512];                // per-block totals
__device__ int    g_boff[512];                // exclusive scan of block totals
__device__ int    g_rowptr[N_NODES];          // CSR row starts
__device__ int    g_fill[N_NODES];            // fill cursors
__device__ float2 g_edge[EDGE_MAX];           // (src as int bits, nrm)
__device__ float  g_h1[N_NODES * F_HID];      // x @ W1
__device__ float  g_agg1[N_NODES * F_HID];    // relu(agg + self + b1)
__device__ float  g_h2[N_NODES * F_OUT];      // relu_out @ W2

// ---------------------------------------------------------------------------
// Packed f32x2 helpers (Blackwell FFMA2 path)
// ---------------------------------------------------------------------------
__device__ __forceinline__ unsigned long long f2pack(float lo, float hi) {
    unsigned long long r;
    asm("mov.b64 %0, {%1, %2};" : "=l"(r) : "f"(lo), "f"(hi));
    return r;
}
__device__ __forceinline__ void f2unpack(unsigned long long v, float& lo, float& hi) {
    asm("mov.b64 {%0, %1}, %2;" : "=f"(lo), "=f"(hi) : "l"(v));
}
__device__ __forceinline__ void fma2(unsigned long long& d,
                                     unsigned long long a, unsigned long long b) {
    asm("fma.rn.f32x2 %0, %1, %2, %0;" : "+l"(d) : "l"(a), "l"(b));
}
__device__ __forceinline__ void lds_v2u64(unsigned long long& a, unsigned long long& b,
                                          const void* p) {
    unsigned s = (unsigned)__cvta_generic_to_shared(p);
    asm volatile("ld.shared.v2.u64 {%0, %1}, [%2];" : "=l"(a), "=l"(b) : "r"(s));
}

// ---------------------------------------------------------------------------
// CSR build
// ---------------------------------------------------------------------------
__global__ void k_zero_cd(int n) {
    int i = blockIdx.x * blockDim.x + threadIdx.x;
    if (i < n) { g_cnt[i] = 0; g_deg[i] = 0.0f; }
}

__global__ void k_count(const int* __restrict__ ei,
                        const float* __restrict__ ew, int E) {
    int e = blockIdx.x * blockDim.x + threadIdx.x;
    if (e < E) {
        int c = ei[E + e];
        atomicAdd(&g_cnt[c], 1);
        atomicAdd(&g_deg[c], ew[e]);
    }
}

__global__ void k_dis(int n) {
    int i = blockIdx.x * blockDim.x + threadIdx.x;
    if (i < n) g_dis[i] = rsqrtf(g_deg[i] + 1.0f);   // +1 = self-loop weight
}

// exclusive scan, stage 1: 256-element chunks
__global__ void k_scan_local(int n) {
    __shared__ int s[256];
    int tid = threadIdx.x;
    int gid = blockIdx.x * 256 + tid;
    int v = (gid < n) ? g_cnt[gid] : 0;
    s[tid] = v;
    #pragma unroll
    for (int off = 1; off < 256; off <<= 1) {
        __syncthreads();
        int t = (tid >= off) ? s[tid - off] : 0;
        __syncthreads();
        s[tid] += t;
    }
    __syncthreads();
    if (gid < n) g_excl[gid] = s[tid] - v;
    if (tid == 255) g_bsum[blockIdx.x] = s[255];
}

// stage 2: scan block sums (<=512)
__global__ void k_scan_bsum(int nb) {
    __shared__ int s[512];
    int tid = threadIdx.x;
    int v = (tid < nb) ? g_bsum[tid] : 0;
    s[tid] = v;
    #pragma unroll
    for (int off = 1; off < 512; off <<= 1) {
        __syncthreads();
        int t = (tid >= off) ? s[tid - off] : 0;
        __syncthreads();
        s[tid] += t;
    }
    __syncthreads();
    if (tid < nb) g_boff[tid] = s[tid] - v;
}

// stage 3: combine, init rowptr + fill cursor
__global__ void k_scan_add(int n) {
    int i = blockIdx.x * blockDim.x + threadIdx.x;
    if (i < n) {
        int v = g_excl[i] + g_boff[i >> 8];
        g_rowptr[i] = v;
        g_fill[i]   = v;
    }
}

// scatter edges into CSR; precompute nrm = dis[src]*w*dis[dst]
__global__ void k_fill(const int* __restrict__ ei,
                       const float* __restrict__ ew, int E) {
    int e = blockIdx.x * blockDim.x + threadIdx.x;
    if (e >= E) return;
    int r = ei[e];
    int c = ei[E + e];
    float nrm = g_dis[r] * ew[e] * g_dis[c];
    int pos = atomicAdd(&g_fill[c], 1);
    g_edge[pos] = make_float2(__int_as_float(r), nrm);
}

// ---------------------------------------------------------------------------
// GEMM1: g_h1[N,64] = x[N,256] @ W1[256,64]
// 128 thr, tile 128 rows x 64 cols, each thread 8 rows x 8 cols via FFMA2:
// per k-step: 4x LDS.128 + 8 packs + 32 FMA2 (= 64 FMA). 1.0 B LDS / FMA.
// Grid stays at 782 blocks (occupancy preserved vs 256-row tile).
// ---------------------------------------------------------------------------
#define G1_ROWS 128
#define G1_KCH  32

__global__ void k_gemm1(const float* __restrict__ x,
                        const float* __restrict__ W1) {
    __shared__ float xs[G1_KCH][G1_ROWS];   // 16 KB, k-major
    __shared__ float ws[G1_KCH][F_HID];     // 8 KB,  k-major

    int t    = threadIdx.x;               // 0..127
    int row0 = blockIdx.x * G1_ROWS;
    int tx   = t & 7;         // col group: cols tx*8 .. +7
    int ty   = t >> 3;        // row group: rows ty*8 .. +7 (16 groups)

    // acc2[p][j]: rows (ty*8+2p, ty*8+2p+1), col tx*8+j, packed f32x2
    unsigned long long acc2[4][8];
    #pragma unroll
    for (int p = 0; p < 4; p++)
        #pragma unroll
        for (int j = 0; j < 8; j++) acc2[p][j] = f2pack(0.0f, 0.0f);

    for (int kc = 0; kc < F_IN / G1_KCH; kc++) {
        // W chunk: 32x64 floats = 512 float4
        const float4* w4 = (const float4*)(W1 + kc * G1_KCH * F_HID);
        #pragma unroll
        for (int j = 0; j < 4; j++)
            ((float4*)ws)[t + j * 128] = w4[t + j * 128];
        // x tile: 128 rows x 32 k = 1024 float4, transposed into xs[k][row]
        #pragma unroll
        for (int j = 0; j < 8; j++) {
            int idx = t + j * 128;
            int r   = idx & 127;
            int kq  = idx >> 7;                  // 0..7
            int gr  = row0 + r;
            if (gr >= N_NODES) gr = N_NODES - 1; // clamped read (result discarded)
            float4 v = *(const float4*)(x + (size_t)gr * F_IN + kc * G1_KCH + kq * 4);
            xs[kq * 4 + 0][r] = v.x;
            xs[kq * 4 + 1][r] = v.y;
            xs[kq * 4 + 2][r] = v.z;
            xs[kq * 4 + 3][r] = v.w;
        }
        __syncthreads();

        #pragma unroll
        for (int kk = 0; kk < G1_KCH; kk++) {
            unsigned long long ap0, ap1, ap2, ap3;
            lds_v2u64(ap0, ap1, &xs[kk][ty * 8]);
            lds_v2u64(ap2, ap3, &xs[kk][ty * 8 + 4]);
            float4 b0 = *(const float4*)&ws[kk][tx * 8];
            float4 b1 = *(const float4*)&ws[kk][tx * 8 + 4];
            unsigned long long bd[8];
            bd[0] = f2pack(b0.x, b0.x); bd[1] = f2pack(b0.y, b0.y);
            bd[2] = f2pack(b0.z, b0.z); bd[3] = f2pack(b0.w, b0.w);
            bd[4] = f2pack(b1.x, b1.x); bd[5] = f2pack(b1.y, b1.y);
            bd[6] = f2pack(b1.z, b1.z); bd[7] = f2pack(b1.w, b1.w);
            #pragma unroll
            for (int j = 0; j < 8; j++) {
                fma2(acc2[0][j], ap0, bd[j]);
                fma2(acc2[1][j], ap1, bd[j]);
                fma2(acc2[2][j], ap2, bd[j]);
                fma2(acc2[3][j], ap3, bd[j]);
            }
        }
        __syncthreads();
    }

    #pragma unroll
    for (int p = 0; p < 4; p++) {
        float lo[8], hi[8];
        #pragma unroll
        for (int j = 0; j < 8; j++) f2unpack(acc2[p][j], lo[j], hi[j]);
        int gr0 = row0 + ty * 8 + 2 * p;
        if (gr0 < N_NODES) {
            float* o = g_h1 + (size_t)gr0 * F_HID + tx * 8;
            *(float4*)(o)     = make_float4(lo[0], lo[1], lo[2], lo[3]);
            *(float4*)(o + 4) = make_float4(lo[4], lo[5], lo[6], lo[7]);
        }
        if (gr0 + 1 < N_NODES) {
            float* o = g_h1 + (size_t)(gr0 + 1) * F_HID + tx * 8;
            *(float4*)(o)     = make_float4(hi[0], hi[1], hi[2], hi[3]);
            *(float4*)(o + 4) = make_float4(hi[4], hi[5], hi[6], hi[7]);
        }
    }
}

// ---------------------------------------------------------------------------
// Layer-1 CSR aggregation: 16 threads per node, gather-only, no atomics.
// Fuses self-loop + bias + relu.
// ---------------------------------------------------------------------------
__global__ void k_agg1_csr(const float* __restrict__ b1) {
    int idx  = blockIdx.x * blockDim.x + threadIdx.x;
    int node = idx >> 4;
    int c    = idx & 15;
    if (node >= N_NODES) return;
    int beg = g_rowptr[node];
    int cnt = g_cnt[node];
    float di = g_dis[node];

    float4 acc = make_float4(0.f, 0.f, 0.f, 0.f);
    int j = 0;
    for (; j + 1 < cnt; j += 2) {
        float2 e0 = g_edge[beg + j];
        float2 e1 = g_edge[beg + j + 1];
        int s0 = __float_as_int(e0.x);
        int s1 = __float_as_int(e1.x);
        float4 v0 = *(const float4*)(g_h1 + (size_t)s0 * F_HID + c * 4);
        float4 v1 = *(const float4*)(g_h1 + (size_t)s1 * F_HID + c * 4);
        acc.x += e0.y * v0.x + e1.y * v1.x;
        acc.y += e0.y * v0.y + e1.y * v1.y;
        acc.z += e0.y * v0.z + e1.y * v1.z;
        acc.w += e0.y * v0.w + e1.y * v1.w;
    }
    if (j < cnt) {
        float2 e0 = g_edge[beg + j];
        int s0 = __float_as_int(e0.x);
        float4 v0 = *(const float4*)(g_h1 + (size_t)s0 * F_HID + c * 4);
        acc.x += e0.y * v0.x;
        acc.y += e0.y * v0.y;
        acc.z += e0.y * v0.z;
        acc.w += e0.y * v0.w;
    }

    float s2 = di * di;
    float4 h = *(const float4*)(g_h1 + (size_t)node * F_HID + c * 4);
    float4 b = ((const float4*)b1)[c];
    float4 o;
    o.x = fmaxf(acc.x + s2 * h.x + b.x, 0.0f);
    o.y = fmaxf(acc.y + s2 * h.y + b.y, 0.0f);
    o.z = fmaxf(acc.z + s2 * h.z + b.z, 0.0f);
    o.w = fmaxf(acc.w + s2 * h.w + b.w, 0.0f);
    *(float4*)(g_agg1 + (size_t)node * F_HID + c * 4) = o;
}

// ---------------------------------------------------------------------------
// GEMM2: g_h2[N,40] = g_agg1[N,64] @ W2[64,40]   (R6 config)
// ---------------------------------------------------------------------------
#define G2_ROWS 128

__global__ void k_gemm2(const float* __restrict__ W2) {
    __shared__ float rs[F_HID][G2_ROWS];   // 32 KB, k-major
    __shared__ float ws2[F_HID][F_OUT];    // 10 KB

    int t    = threadIdx.x;
    int row0 = blockIdx.x * G2_ROWS;
    int tx   = t & 7;         // cols tx*5 .. +4
    int ty   = t >> 3;        // rows ty*4 .. +3

    #pragma unroll
    for (int j = 0; j < 3; j++) {
        int i = t + j * 256;
        if (i < 640) ((float4*)ws2)[i] = ((const float4*)W2)[i];
    }
    #pragma unroll
    for (int j = 0; j < 8; j++) {
        int idx = t + j * 256;
        int r   = idx & 127;
        int kq  = idx >> 7;
        int gr  = row0 + r;
        if (gr >= N_NODES) gr = N_NODES - 1;
        float4 v = *(const float4*)(g_agg1 + (size_t)gr * F_HID + kq * 4);
        rs[kq * 4 + 0][r] = v.x;
        rs[kq * 4 + 1][r] = v.y;
        rs[kq * 4 + 2][r] = v.z;
        rs[kq * 4 + 3][r] = v.w;
    }
    __syncthreads();

    unsigned long long acc2[2][5];
    #pragma unroll
    for (int p = 0; p < 2; p++)
        #pragma unroll
        for (int j = 0; j < 5; j++) acc2[p][j] = f2pack(0.0f, 0.0f);

    #pragma unroll
    for (int kk = 0; kk < F_HID; kk++) {
        unsigned long long ap0, ap1;
        lds_v2u64(ap0, ap1, &rs[kk][ty * 4]);
        const float* wrow = &ws2[kk][tx * 5];
        #pragma unroll
        for (int j = 0; j < 5; j++) {
            float bj = wrow[j];
            unsigned long long bd = f2pack(bj, bj);
            fma2(acc2[0][j], ap0, bd);
            fma2(acc2[1][j], ap1, bd);
        }
    }

    #pragma unroll
    for (int p = 0; p < 2; p++) {
        float lo[5], hi[5];
        #pragma unroll
        for (int j = 0; j < 5; j++) f2unpack(acc2[p][j], lo[j], hi[j]);
        int gr0 = row0 + ty * 4 + 2 * p;
        if (gr0 < N_NODES) {
            float* o = g_h2 + (size_t)gr0 * F_OUT + tx * 5;
            #pragma unroll
            for (int j = 0; j < 5; j++) o[j] = lo[j];
        }
        if (gr0 + 1 < N_NODES) {
            float* o = g_h2 + (size_t)(gr0 + 1) * F_OUT + tx * 5;
            #pragma unroll
            for (int j = 0; j < 5; j++) o[j] = hi[j];
        }
    }
}

// ---------------------------------------------------------------------------
// Layer-2 CSR aggregation: 10 threads/node (all active), fuses b2 + self-loop.
// ---------------------------------------------------------------------------
__global__ void k_agg2_csr(const float* __restrict__ b2,
                           float* __restrict__ out) {
    int idx  = blockIdx.x * blockDim.x + threadIdx.x;
    int node = idx / 10;
    int c    = idx - node * 10;
    if (node >= N_NODES) return;
    int beg = g_rowptr[node];
    int cnt = g_cnt[node];
    float di = g_dis[node];

    float4 acc = make_float4(0.f, 0.f, 0.f, 0.f);
    int j = 0;
    for (; j + 1 < cnt; j += 2) {
        float2 e0 = g_edge[beg + j];
        float2 e1 = g_edge[beg + j + 1];
        int s0 = __float_as_int(e0.x);
        int s1 = __float_as_int(e1.x);
        float4 v0 = *(const float4*)(g_h2 + (size_t)s0 * F_OUT + c * 4);
        float4 v1 = *(const float4*)(g_h2 + (size_t)s1 * F_OUT + c * 4);
        acc.x += e0.y * v0.x + e1.y * v1.x;
        acc.y += e0.y * v0.y + e1.y * v1.y;
        acc.z += e0.y * v0.z + e1.y * v1.z;
        acc.w += e0.y * v0.w + e1.y * v1.w;
    }
    if (j < cnt) {
        float2 e0 = g_edge[beg + j];
        int s0 = __float_as_int(e0.x);
        float4 v0 = *(const float4*)(g_h2 + (size_t)s0 * F_OUT + c * 4);
        acc.x += e0.y * v0.x;
        acc.y += e0.y * v0.y;
        acc.z += e0.y * v0.z;
        acc.w += e0.y * v0.w;
    }

    float s2 = di * di;
    float4 h = *(const float4*)(g_h2 + (size_t)node * F_OUT + c * 4);
    float4 b = ((const float4*)b2)[c];
    float4 o;
    o.x = acc.x + s2 * h.x + b.x;
    o.y = acc.y + s2 * h.y + b.y;
    o.z = acc.z + s2 * h.z + b.z;
    o.w = acc.w + s2 * h.w + b.w;
    *(float4*)(out + (size_t)node * F_OUT + c * 4) = o;
}

// ---------------------------------------------------------------------------
extern "C" void kernel_launch(void* const* d_in, const int* in_sizes, int n_in,
                              void* d_out, int out_size) {
    const float* x  = (const float*)d_in[0];
    const int*   ei = (const int*)d_in[1];
    const float* ew = (const float*)d_in[2];
    const float* W1 = (const float*)d_in[3];
    const float* b1 = (const float*)d_in[4];
    const float* W2 = (const float*)d_in[5];
    const float* b2 = (const float*)d_in[6];
    float* out = (float*)d_out;

    int N = in_sizes[0] / F_IN;     // 100000
    int E = in_sizes[2];            // 1600000
    int nblk = (N + 255) / 256;     // 391

    // CSR build + normalization
    k_zero_cd<<<nblk, 256>>>(N);
    k_count<<<(E + 255) / 256, 256>>>(ei, ew, E);
    k_dis<<<nblk, 256>>>(N);
    k_scan_local<<<nblk, 256>>>(N);
    k_scan_bsum<<<1, 512>>>(nblk);
    k_scan_add<<<nblk, 256>>>(N);
    k_fill<<<(E + 255) / 256, 256>>>(ei, ew, E);

    // layer 1
    k_gemm1<<<(N + G1_ROWS - 1) / G1_ROWS, 128>>>(x, W1);
    {
        long long items = (long long)N * 16;
        k_agg1_csr<<<(int)((items + 255) / 256), 256>>>(b1);
    }

    // layer 2
    k_gemm2<<<(N + G2_ROWS - 1) / G2_ROWS, 256>>>(W2);
    {
        long long items = (long long)N * 10;
        k_agg2_csr<<<(int)((items + 255) / 256), 256>>>(b2, out);
    }
}

// round 10
// speedup vs baseline: 1.1080x; 1.1080x over previous
#include <cuda_runtime.h>

#define N_NODES  100000
#define F_IN     256
#define F_HID    64
#define F_OUT    40
#define EDGE_MAX 1700000

// Scratch (static device globals — no allocation allowed)
__device__ float  g_dis[N_NODES];             // rsqrt(weighted deg + 1)
__device__ float  g_deg[N_NODES];             // weighted degree accumulator
__device__ int    g_cnt[N_NODES];             // edges per destination
__device__ int    g_excl[N_NODES];            // local exclusive scan
__device__ int    g_bsum[512];                // per-block totals
__device__ int    g_boff[512];                // exclusive scan of block totals
__device__ int    g_rowptr[N_NODES];          // CSR row starts
__device__ int    g_fill[N_NODES];            // fill cursors
__device__ float2 g_edge[EDGE_MAX];           // (src as int bits, nrm)
__device__ float  g_h1[N_NODES * F_HID];      // x @ W1
__device__ float  g_agg1[N_NODES * F_HID];    // relu(agg + self + b1)
__device__ float  g_h2[N_NODES * F_OUT];      // relu_out @ W2

// ---------------------------------------------------------------------------
// Packed f32x2 helpers (Blackwell FFMA2 path)
// ---------------------------------------------------------------------------
__device__ __forceinline__ unsigned long long f2pack(float lo, float hi) {
    unsigned long long r;
    asm("mov.b64 %0, {%1, %2};" : "=l"(r) : "f"(lo), "f"(hi));
    return r;
}
__device__ __forceinline__ void f2unpack(unsigned long long v, float& lo, float& hi) {
    asm("mov.b64 {%0, %1}, %2;" : "=f"(lo), "=f"(hi) : "l"(v));
}
__device__ __forceinline__ void fma2(unsigned long long& d,
                                     unsigned long long a, unsigned long long b) {
    asm("fma.rn.f32x2 %0, %1, %2, %0;" : "+l"(d) : "l"(a), "l"(b));
}
__device__ __forceinline__ void lds_v2u64(unsigned long long& a, unsigned long long& b,
                                          const void* p) {
    unsigned s = (unsigned)__cvta_generic_to_shared(p);
    asm volatile("ld.shared.v2.u64 {%0, %1}, [%2];" : "=l"(a), "=l"(b) : "r"(s));
}

// ---------------------------------------------------------------------------
// CSR build
// ---------------------------------------------------------------------------
__global__ void k_zero_cd(int n) {
    int i = blockIdx.x * blockDim.x + threadIdx.x;
    if (i < n) { g_cnt[i] = 0; g_deg[i] = 0.0f; }
}

__global__ void k_count(const int* __restrict__ ei,
                        const float* __restrict__ ew, int E) {
    int e = blockIdx.x * blockDim.x + threadIdx.x;
    if (e < E) {
        int c = ei[E + e];
        atomicAdd(&g_cnt[c], 1);
        atomicAdd(&g_deg[c], ew[e]);
    }
}

// exclusive scan, stage 1: 256-element chunks
__global__ void k_scan_local(int n) {
    __shared__ int s[256];
    int tid = threadIdx.x;
    int gid = blockIdx.x * 256 + tid;
    int v = (gid < n) ? g_cnt[gid] : 0;
    s[tid] = v;
    #pragma unroll
    for (int off = 1; off < 256; off <<= 1) {
        __syncthreads();
        int t = (tid >= off) ? s[tid - off] : 0;
        __syncthreads();
        s[tid] += t;
    }
    __syncthreads();
    if (gid < n) g_excl[gid] = s[tid] - v;
    if (tid == 255) g_bsum[blockIdx.x] = s[255];
}

// stage 2: scan block sums (<=512)
__global__ void k_scan_bsum(int nb) {
    __shared__ int s[512];
    int tid = threadIdx.x;
    int v = (tid < nb) ? g_bsum[tid] : 0;
    s[tid] = v;
    #pragma unroll
    for (int off = 1; off < 512; off <<= 1) {
        __syncthreads();
        int t = (tid >= off) ? s[tid - off] : 0;
        __syncthreads();
        s[tid] += t;
    }
    __syncthreads();
    if (tid < nb) g_boff[tid] = s[tid] - v;
}

// stage 3: combine scan, init rowptr + fill cursor; fused dis = rsqrt(deg+1)
__global__ void k_scan_add(int n) {
    int i = blockIdx.x * blockDim.x + threadIdx.x;
    if (i < n) {
        int v = g_excl[i] + g_boff[i >> 8];
        g_rowptr[i] = v;
        g_fill[i]   = v;
        g_dis[i]    = rsqrtf(g_deg[i] + 1.0f);   // +1 = self-loop weight
    }
}

// scatter edges into CSR; precompute nrm = dis[src]*w*dis[dst]
__global__ void k_fill(const int* __restrict__ ei,
                       const float* __restrict__ ew, int E) {
    int e = blockIdx.x * blockDim.x + threadIdx.x;
    if (e >= E) return;
    int r = ei[e];
    int c = ei[E + e];
    float nrm = g_dis[r] * ew[e] * g_dis[c];
    int pos = atomicAdd(&g_fill[c], 1);
    g_edge[pos] = make_float2(__int_as_float(r), nrm);
}

// ---------------------------------------------------------------------------
// GEMM1: g_h1[N,64] = x[N,256] @ W1[256,64]   (R6/R8 winner config)
// 256 thr, tile 128 rows x 64 cols, 8 rows x 4 cols per thread via FFMA2.
// ---------------------------------------------------------------------------
#define G1_ROWS 128
#define G1_KCH  32

__global__ void k_gemm1(const float* __restrict__ x,
                        const float* __restrict__ W1) {
    __shared__ float xs[G1_KCH][G1_ROWS];   // 16 KB, k-major
    __shared__ float ws[G1_KCH][F_HID];     // 8 KB,  k-major

    int t    = threadIdx.x;
    int row0 = blockIdx.x * G1_ROWS;
    int tx   = t & 15;        // col group: cols tx*4 .. +3
    int ty   = t >> 4;        // row group: rows ty*8 .. +7

    unsigned long long acc2[4][4];
    #pragma unroll
    for (int p = 0; p < 4; p++)
        #pragma unroll
        for (int j = 0; j < 4; j++) acc2[p][j] = f2pack(0.0f, 0.0f);

    for (int kc = 0; kc < F_IN / G1_KCH; kc++) {
        const float4* w4 = (const float4*)(W1 + kc * G1_KCH * F_HID);
        ((float4*)ws)[t]       = w4[t];
        ((float4*)ws)[t + 256] = w4[t + 256];
        #pragma unroll
        for (int j = 0; j < 4; j++) {
            int idx = t + j * 256;
            int r   = idx & 127;
            int kq  = idx >> 7;
            int gr  = row0 + r;
            if (gr >= N_NODES) gr = N_NODES - 1;
            float4 v = *(const float4*)(x + (size_t)gr * F_IN + kc * G1_KCH + kq * 4);
            xs[kq * 4 + 0][r] = v.x;
            xs[kq * 4 + 1][r] = v.y;
            xs[kq * 4 + 2][r] = v.z;
            xs[kq * 4 + 3][r] = v.w;
        }
        __syncthreads();

        #pragma unroll
        for (int kk = 0; kk < G1_KCH; kk++) {
            unsigned long long ap0, ap1, ap2, ap3;
            lds_v2u64(ap0, ap1, &xs[kk][ty * 8]);
            lds_v2u64(ap2, ap3, &xs[kk][ty * 8 + 4]);
            float4 b = *(const float4*)&ws[kk][tx * 4];
            unsigned long long bd0 = f2pack(b.x, b.x);
            unsigned long long bd1 = f2pack(b.y, b.y);
            unsigned long long bd2 = f2pack(b.z, b.z);
            unsigned long long bd3 = f2pack(b.w, b.w);
            fma2(acc2[0][0], ap0, bd0); fma2(acc2[0][1], ap0, bd1);
            fma2(acc2[0][2], ap0, bd2); fma2(acc2[0][3], ap0, bd3);
            fma2(acc2[1][0], ap1, bd0); fma2(acc2[1][1], ap1, bd1);
            fma2(acc2[1][2], ap1, bd2); fma2(acc2[1][3], ap1, bd3);
            fma2(acc2[2][0], ap2, bd0); fma2(acc2[2][1], ap2, bd1);
            fma2(acc2[2][2], ap2, bd2); fma2(acc2[2][3], ap2, bd3);
            fma2(acc2[3][0], ap3, bd0); fma2(acc2[3][1], ap3, bd1);
            fma2(acc2[3][2], ap3, bd2); fma2(acc2[3][3], ap3, bd3);
        }
        __syncthreads();
    }

    #pragma unroll
    for (int p = 0; p < 4; p++) {
        float lo0, hi0, lo1, hi1, lo2, hi2, lo3, hi3;
        f2unpack(acc2[p][0], lo0, hi0);
        f2unpack(acc2[p][1], lo1, hi1);
        f2unpack(acc2[p][2], lo2, hi2);
        f2unpack(acc2[p][3], lo3, hi3);
        int gr0 = row0 + ty * 8 + 2 * p;
        if (gr0 < N_NODES)
            *(float4*)(g_h1 + (size_t)gr0 * F_HID + tx * 4) =
                make_float4(lo0, lo1, lo2, lo3);
        if (gr0 + 1 < N_NODES)
            *(float4*)(g_h1 + (size_t)(gr0 + 1) * F_HID + tx * 4) =
                make_float4(hi0, hi1, hi2, hi3);
    }
}

// ---------------------------------------------------------------------------
// Layer-1 CSR aggregation: 16 threads per node, gather-only, no atomics.
// Fuses self-loop + bias + relu.
// ---------------------------------------------------------------------------
__global__ void k_agg1_csr(const float* __restrict__ b1) {
    int idx  = blockIdx.x * blockDim.x + threadIdx.x;
    int node = idx >> 4;
    int c    = idx & 15;
    if (node >= N_NODES) return;
    int beg = g_rowptr[node];
    int cnt = g_cnt[node];
    float di = g_dis[node];

    float4 acc = make_float4(0.f, 0.f, 0.f, 0.f);
    int j = 0;
    for (; j + 1 < cnt; j += 2) {
        float2 e0 = g_edge[beg + j];
        float2 e1 = g_edge[beg + j + 1];
        int s0 = __float_as_int(e0.x);
        int s1 = __float_as_int(e1.x);
        float4 v0 = *(const float4*)(g_h1 + (size_t)s0 * F_HID + c * 4);
        float4 v1 = *(const float4*)(g_h1 + (size_t)s1 * F_HID + c * 4);
        acc.x += e0.y * v0.x + e1.y * v1.x;
        acc.y += e0.y * v0.y + e1.y * v1.y;
        acc.z += e0.y * v0.z + e1.y * v1.z;
        acc.w += e0.y * v0.w + e1.y * v1.w;
    }
    if (j < cnt) {
        float2 e0 = g_edge[beg + j];
        int s0 = __float_as_int(e0.x);
        float4 v0 = *(const float4*)(g_h1 + (size_t)s0 * F_HID + c * 4);
        acc.x += e0.y * v0.x;
        acc.y += e0.y * v0.y;
        acc.z += e0.y * v0.z;
        acc.w += e0.y * v0.w;
    }

    float s2 = di * di;
    float4 h = *(const float4*)(g_h1 + (size_t)node * F_HID + c * 4);
    float4 b = ((const float4*)b1)[c];
    float4 o;
    o.x = fmaxf(acc.x + s2 * h.x + b.x, 0.0f);
    o.y = fmaxf(acc.y + s2 * h.y + b.y, 0.0f);
    o.z = fmaxf(acc.z + s2 * h.z + b.z, 0.0f);
    o.w = fmaxf(acc.w + s2 * h.w + b.w, 0.0f);
    *(float4*)(g_agg1 + (size_t)node * F_HID + c * 4) = o;
}

// ---------------------------------------------------------------------------
// GEMM2: g_h2[N,40] = g_agg1[N,64] @ W2[64,40]   (R6 config)
// ---------------------------------------------------------------------------
#define G2_ROWS 128

__global__ void k_gemm2(const float* __restrict__ W2) {
    __shared__ float rs[F_HID][G2_ROWS];   // 32 KB, k-major
    __shared__ float ws2[F_HID][F_OUT];    // 10 KB

    int t    = threadIdx.x;
    int row0 = blockIdx.x * G2_ROWS;
    int tx   = t & 7;         // cols tx*5 .. +4
    int ty   = t >> 3;        // rows ty*4 .. +3

    #pragma unroll
    for (int j = 0; j < 3; j++) {
        int i = t + j * 256;
        if (i < 640) ((float4*)ws2)[i] = ((const float4*)W2)[i];
    }
    #pragma unroll
    for (int j = 0; j < 8; j++) {
        int idx = t + j * 256;
        int r   = idx & 127;
        int kq  = idx >> 7;
        int gr  = row0 + r;
        if (gr >= N_NODES) gr = N_NODES - 1;
        float4 v = *(const float4*)(g_agg1 + (size_t)gr * F_HID + kq * 4);
        rs[kq * 4 + 0][r] = v.x;
        rs[kq * 4 + 1][r] = v.y;
        rs[kq * 4 + 2][r] = v.z;
        rs[kq * 4 + 3][r] = v.w;
    }
    __syncthreads();

    unsigned long long acc2[2][5];
    #pragma unroll
    for (int p = 0; p < 2; p++)
        #pragma unroll
        for (int j = 0; j < 5; j++) acc2[p][j] = f2pack(0.0f, 0.0f);

    #pragma unroll
    for (int kk = 0; kk < F_HID; kk++) {
        unsigned long long ap0, ap1;
        lds_v2u64(ap0, ap1, &rs[kk][ty * 4]);
        const float* wrow = &ws2[kk][tx * 5];
        #pragma unroll
        for (int j = 0; j < 5; j++) {
            float bj = wrow[j];
            unsigned long long bd = f2pack(bj, bj);
            fma2(acc2[0][j], ap0, bd);
            fma2(acc2[1][j], ap1, bd);
        }
    }

    #pragma unroll
    for (int p = 0; p < 2; p++) {
        float lo[5], hi[5];
        #pragma unroll
        for (int j = 0; j < 5; j++) f2unpack(acc2[p][j], lo[j], hi[j]);
        int gr0 = row0 + ty * 4 + 2 * p;
        if (gr0 < N_NODES) {
            float* o = g_h2 + (size_t)gr0 * F_OUT + tx * 5;
            #pragma unroll
            for (int j = 0; j < 5; j++) o[j] = lo[j];
        }
        if (gr0 + 1 < N_NODES) {
            float* o = g_h2 + (size_t)(gr0 + 1) * F_OUT + tx * 5;
            #pragma unroll
            for (int j = 0; j < 5; j++) o[j] = hi[j];
        }
    }
}

// ---------------------------------------------------------------------------
// Layer-2 CSR aggregation: 10 threads/node (all active), fuses b2 + self-loop.
// ---------------------------------------------------------------------------
__global__ void k_agg2_csr(const float* __restrict__ b2,
                           float* __restrict__ out) {
    int idx  = blockIdx.x * blockDim.x + threadIdx.x;
    int node = idx / 10;
    int c    = idx - node * 10;
    if (node >= N_NODES) return;
    int beg = g_rowptr[node];
    int cnt = g_cnt[node];
    float di = g_dis[node];

    float4 acc = make_float4(0.f, 0.f, 0.f, 0.f);
    int j = 0;
    for (; j + 1 < cnt; j += 2) {
        float2 e0 = g_edge[beg + j];
        float2 e1 = g_edge[beg + j + 1];
        int s0 = __float_as_int(e0.x);
        int s1 = __float_as_int(e1.x);
        float4 v0 = *(const float4*)(g_h2 + (size_t)s0 * F_OUT + c * 4);
        float4 v1 = *(const float4*)(g_h2 + (size_t)s1 * F_OUT + c * 4);
        acc.x += e0.y * v0.x + e1.y * v1.x;
        acc.y += e0.y * v0.y + e1.y * v1.y;
        acc.z += e0.y * v0.z + e1.y * v1.z;
        acc.w += e0.y * v0.w + e1.y * v1.w;
    }
    if (j < cnt) {
        float2 e0 = g_edge[beg + j];
        int s0 = __float_as_int(e0.x);
        float4 v0 = *(const float4*)(g_h2 + (size_t)s0 * F_OUT + c * 4);
        acc.x += e0.y * v0.x;
        acc.y += e0.y * v0.y;
        acc.z += e0.y * v0.z;
        acc.w += e0.y * v0.w;
    }

    float s2 = di * di;
    float4 h = *(const float4*)(g_h2 + (size_t)node * F_OUT + c * 4);
    float4 b = ((const float4*)b2)[c];
    float4 o;
    o.x = acc.x + s2 * h.x + b.x;
    o.y = acc.y + s2 * h.y + b.y;
    o.z = acc.z + s2 * h.z + b.z;
    o.w = acc.w + s2 * h.w + b.w;
    *(float4*)(out + (size_t)node * F_OUT + c * 4) = o;
}

// ---------------------------------------------------------------------------
extern "C" void kernel_launch(void* const* d_in, const int* in_sizes, int n_in,
                              void* d_out, int out_size) {
    const float* x  = (const float*)d_in[0];
    const int*   ei = (const int*)d_in[1];
    const float* ew = (const float*)d_in[2];
    const float* W1 = (const float*)d_in[3];
    const float* b1 = (const float*)d_in[4];
    const float* W2 = (const float*)d_in[5];
    const float* b2 = (const float*)d_in[6];
    float* out = (float*)d_out;

    int N = in_sizes[0] / F_IN;     // 100000
    int E = in_sizes[2];            // 1600000
    int nblk = (N + 255) / 256;     // 391

    // CSR build + normalization
    k_zero_cd<<<nblk, 256>>>(N);
    k_count<<<(E + 255) / 256, 256>>>(ei, ew, E);
    k_scan_local<<<nblk, 256>>>(N);
    k_scan_bsum<<<1, 512>>>(nblk);
    k_scan_add<<<nblk, 256>>>(N);      // also computes g_dis
    k_fill<<<(E + 255) / 256, 256>>>(ei, ew, E);

    // layer 1
    k_gemm1<<<(N + G1_ROWS - 1) / G1_ROWS, 256>>>(x, W1);
    {
        long long items = (long long)N * 16;
        k_agg1_csr<<<(int)((items + 255) / 256), 256>>>(b1);
    }

    // layer 2
    k_gemm2<<<(N + G2_ROWS - 1) / G2_ROWS, 256>>>(W2);
    {
        long long items = (long long)N * 10;
        k_agg2_csr<<<(int)((items + 255) / 256), 256>>>(b2, out);
    }
}

// round 11
// speedup vs baseline: 1.2081x; 1.0904x over previous
#include <cuda_runtime.h>

#define N_NODES  100000
#define F_IN     256
#define F_HID    64
#define F_OUT    40
#define EDGE_MAX 1700000

// Scratch (static device globals — no allocation allowed)
__device__ float  g_dis[N_NODES];             // rsqrt(weighted deg + 1)
__device__ float  g_deg[N_NODES];             // weighted degree accumulator
__device__ int    g_cnt[N_NODES];             // edges per destination
__device__ int    g_excl[N_NODES];            // local exclusive scan
__device__ int    g_bsum[512];                // per-block totals
__device__ int    g_rowptr[N_NODES];          // CSR row starts
__device__ int    g_fill[N_NODES];            // fill cursors
__device__ float2 g_edge[EDGE_MAX];           // (src as int bits, nrm)
__device__ float  g_w1hi[F_IN * F_HID];       // tf32-rounded W1
__device__ float  g_w1lo[F_IN * F_HID];       // tf32 residual of W1
__device__ float  g_h1[N_NODES * F_HID];      // x @ W1
__device__ float  g_agg1[N_NODES * F_HID];    // relu(agg + self + b1)
__device__ float  g_h2[N_NODES * F_OUT];      // relu_out @ W2

// ---------------------------------------------------------------------------
// Packed f32x2 helpers (FFMA2 path, used by gemm2)
// ---------------------------------------------------------------------------
__device__ __forceinline__ unsigned long long f2pack(float lo, float hi) {
    unsigned long long r;
    asm("mov.b64 %0, {%1, %2};" : "=l"(r) : "f"(lo), "f"(hi));
    return r;
}
__device__ __forceinline__ void f2unpack(unsigned long long v, float& lo, float& hi) {
    asm("mov.b64 {%0, %1}, %2;" : "=f"(lo), "=f"(hi) : "l"(v));
}
__device__ __forceinline__ void fma2(unsigned long long& d,
                                     unsigned long long a, unsigned long long b) {
    asm("fma.rn.f32x2 %0, %1, %2, %0;" : "+l"(d) : "l"(a), "l"(b));
}
__device__ __forceinline__ void lds_v2u64(unsigned long long& a, unsigned long long& b,
                                          const void* p) {
    unsigned s = (unsigned)__cvta_generic_to_shared(p);
    asm volatile("ld.shared.v2.u64 {%0, %1}, [%2];" : "=l"(a), "=l"(b) : "r"(s));
}

// ---------------------------------------------------------------------------
// tf32 helpers
// ---------------------------------------------------------------------------
__device__ __forceinline__ unsigned to_tf32(float f) {
    unsigned r;
    asm("cvt.rna.tf32.f32 %0, %1;" : "=r"(r) : "f"(f));
    return r;
}
__device__ __forceinline__ void mma_tf32(float c[4], const unsigned a[4],
                                         const unsigned b[2]) {
    asm volatile(
        "mma.sync.aligned.m16n8k8.row.col.f32.tf32.tf32.f32 "
        "{%0,%1,%2,%3}, {%4,%5,%6,%7}, {%8,%9}, {%0,%1,%2,%3};\n"
        : "+f"(c[0]), "+f"(c[1]), "+f"(c[2]), "+f"(c[3])
        : "r"(a[0]), "r"(a[1]), "r"(a[2]), "r"(a[3]), "r"(b[0]), "r"(b[1]));
}

// ---------------------------------------------------------------------------
// CSR build
// ---------------------------------------------------------------------------
__global__ void k_zero_cd(int n) {
    int i = blockIdx.x * blockDim.x + threadIdx.x;
    if (i < n) { g_cnt[i] = 0; g_deg[i] = 0.0f; }
}

__global__ void k_count(const int* __restrict__ ei,
                        const float* __restrict__ ew, int E) {
    int e = blockIdx.x * blockDim.x + threadIdx.x;
    if (e < E) {
        int c = ei[E + e];
        atomicAdd(&g_cnt[c], 1);
        atomicAdd(&g_deg[c], ew[e]);
    }
}

// W1 tf32 hi/lo split (one-time, tiny)
__global__ void k_splitW1(const float* __restrict__ W1) {
    int i = blockIdx.x * blockDim.x + threadIdx.x;
    if (i < F_IN * F_HID) {
        float f = W1[i];
        float hf = __uint_as_float(to_tf32(f));
        g_w1hi[i] = hf;
        g_w1lo[i] = __uint_as_float(to_tf32(f - hf));
    }
}

// exclusive scan, stage 1: 256-element chunks
__global__ void k_scan_local(int n) {
    __shared__ int s[256];
    int tid = threadIdx.x;
    int gid = blockIdx.x * 256 + tid;
    int v = (gid < n) ? g_cnt[gid] : 0;
    s[tid] = v;
    #pragma unroll
    for (int off = 1; off < 256; off <<= 1) {
        __syncthreads();
        int t = (tid >= off) ? s[tid - off] : 0;
        __syncthreads();
        s[tid] += t;
    }
    __syncthreads();
    if (gid < n) g_excl[gid] = s[tid] - v;
    if (tid == 255) g_bsum[blockIdx.x] = s[255];
}

// stage 2 (fused): each block reduces bsum[0..bid) inline; init rowptr/fill/dis
__global__ void k_scan_add(int n) {
    __shared__ int red[256];
    int tid = threadIdx.x;
    int bid = blockIdx.x;
    int s = 0;
    for (int j = tid; j < bid; j += 256) s += g_bsum[j];
    red[tid] = s;
    __syncthreads();
    #pragma unroll
    for (int off = 128; off > 0; off >>= 1) {
        if (tid < off) red[tid] += red[tid + off];
        __syncthreads();
    }
    int base = red[0];
    int i = bid * 256 + tid;
    if (i < n) {
        int v = g_excl[i] + base;
        g_rowptr[i] = v;
        g_fill[i]   = v;
        g_dis[i]    = rsqrtf(g_deg[i] + 1.0f);   // +1 = self-loop weight
    }
}

// scatter edges into CSR; precompute nrm = dis[src]*w*dis[dst]
__global__ void k_fill(const int* __restrict__ ei,
                       const float* __restrict__ ew, int E) {
    int e = blockIdx.x * blockDim.x + threadIdx.x;
    if (e >= E) return;
    int r = ei[e];
    int c = ei[E + e];
    float nrm = g_dis[r] * ew[e] * g_dis[c];
    int pos = atomicAdd(&g_fill[c], 1);
    g_edge[pos] = make_float2(__int_as_float(r), nrm);
}

// ---------------------------------------------------------------------------
// GEMM1 (tensor): g_h1[N,64] = x[N,256] @ W1[256,64] via 3xTF32 mma.sync.
// 256 thr = 8 warps; tile 128 rows x 64 cols; warp w -> rows w*16..+15.
// Per k8-step: A frag split hi/lo in regs; W pre-split; 3 mma per n-block.
// Smem pads chosen for conflict-free frag loads (xs stride 36, w stride 72).
// ---------------------------------------------------------------------------
#define G1_ROWS 128

__global__ void k_gemm1(const float* __restrict__ x) {
    __shared__ float xs[G1_ROWS][36];   // 18 KB, row-major, pad 36
    __shared__ float wh[32][72];        // 9 KB, k-major, pad 72
    __shared__ float wl[32][72];        // 9 KB

    int t    = threadIdx.x;
    int lane = t & 31;
    int w    = t >> 5;            // warp 0..7
    int g    = lane >> 2;         // group 0..7
    int tg   = lane & 3;          // 0..3
    int row0 = blockIdx.x * G1_ROWS;
    int rb   = w * 16;

    float c[8][4];
    #pragma unroll
    for (int nb = 0; nb < 8; nb++)
        #pragma unroll
        for (int i = 0; i < 4; i++) c[nb][i] = 0.0f;

    for (int kc = 0; kc < 8; kc++) {            // k-chunks of 32
        // x tile: 128 rows x 32 k = 1024 float4, direct row-major STS.128
        #pragma unroll
        for (int j = 0; j < 4; j++) {
            int idx = t + j * 256;
            int r   = idx >> 3;
            int f4  = idx & 7;
            int gr  = row0 + r;
            if (gr >= N_NODES) gr = N_NODES - 1;   // clamped (result discarded)
            float4 v = *(const float4*)(x + (size_t)gr * F_IN + kc * 32 + f4 * 4);
            *(float4*)&xs[r][f4 * 4] = v;
        }
        // W hi/lo chunks: 32x64 = 512 float4 each
        #pragma unroll
        for (int j = 0; j < 2; j++) {
            int idx = t + j * 256;
            int k   = idx >> 4;
            int n4  = idx & 15;
            const float* src = g_w1hi + kc * 32 * F_HID + k * F_HID + n4 * 4;
            *(float4*)&wh[k][n4 * 4] = *(const float4*)src;
            *(float4*)&wl[k][n4 * 4] = *(const float4*)(src + F_IN * F_HID);
        }
        __syncthreads();

        #pragma unroll
        for (int ks = 0; ks < 4; ks++) {        // 4 k8-steps per chunk
            int k0 = ks * 8;
            float a0 = xs[rb + g][k0 + tg];
            float a1 = xs[rb + g + 8][k0 + tg];
            float a2 = xs[rb + g][k0 + tg + 4];
            float a3 = xs[rb + g + 8][k0 + tg + 4];
            unsigned ahi[4], alo[4];
            ahi[0] = to_tf32(a0); alo[0] = to_tf32(a0 - __uint_as_float(ahi[0]));
            ahi[1] = to_tf32(a1); alo[1] = to_tf32(a1 - __uint_as_float(ahi[1]));
            ahi[2] = to_tf32(a2); alo[2] = to_tf32(a2 - __uint_as_float(ahi[2]));
            ahi[3] = to_tf32(a3); alo[3] = to_tf32(a3 - __uint_as_float(ahi[3]));

            #pragma unroll
            for (int nb = 0; nb < 8; nb++) {
                int n0 = nb * 8;
                unsigned bh[2], bl[2];
                bh[0] = __float_as_uint(wh[k0 + tg][n0 + g]);
                bh[1] = __float_as_uint(wh[k0 + tg + 4][n0 + g]);
                bl[0] = __float_as_uint(wl[k0 + tg][n0 + g]);
                bl[1] = __float_as_uint(wl[k0 + tg + 4][n0 + g]);
                mma_tf32(c[nb], ahi, bh);
                mma_tf32(c[nb], alo, bh);
                mma_tf32(c[nb], ahi, bl);
            }
        }
        __syncthreads();
    }

    int gr0 = row0 + rb + g;
    int gr1 = gr0 + 8;
    #pragma unroll
    for (int nb = 0; nb < 8; nb++) {
        int col = nb * 8 + 2 * tg;
        if (gr0 < N_NODES)
            *(float2*)(g_h1 + (size_t)gr0 * F_HID + col) =
                make_float2(c[nb][0], c[nb][1]);
        if (gr1 < N_NODES)
            *(float2*)(g_h1 + (size_t)gr1 * F_HID + col) =
                make_float2(c[nb][2], c[nb][3]);
    }
}

// ---------------------------------------------------------------------------
// Layer-1 CSR aggregation: 16 threads per node, gather-only, no atomics.
// Fuses self-loop + bias + relu.
// ---------------------------------------------------------------------------
__global__ void k_agg1_csr(const float* __restrict__ b1) {
    int idx  = blockIdx.x * blockDim.x + threadIdx.x;
    int node = idx >> 4;
    int c    = idx & 15;
    if (node >= N_NODES) return;
    int beg = g_rowptr[node];
    int cnt = g_cnt[node];
    float di = g_dis[node];

    float4 acc = make_float4(0.f, 0.f, 0.f, 0.f);
    int j = 0;
    for (; j + 1 < cnt; j += 2) {
        float2 e0 = g_edge[beg + j];
        float2 e1 = g_edge[beg + j + 1];
        int s0 = __float_as_int(e0.x);
        int s1 = __float_as_int(e1.x);
        float4 v0 = *(const float4*)(g_h1 + (size_t)s0 * F_HID + c * 4);
        float4 v1 = *(const float4*)(g_h1 + (size_t)s1 * F_HID + c * 4);
        acc.x += e0.y * v0.x + e1.y * v1.x;
        acc.y += e0.y * v0.y + e1.y * v1.y;
        acc.z += e0.y * v0.z + e1.y * v1.z;
        acc.w += e0.y * v0.w + e1.y * v1.w;
    }
    if (j < cnt) {
        float2 e0 = g_edge[beg + j];
        int s0 = __float_as_int(e0.x);
        float4 v0 = *(const float4*)(g_h1 + (size_t)s0 * F_HID + c * 4);
        acc.x += e0.y * v0.x;
        acc.y += e0.y * v0.y;
        acc.z += e0.y * v0.z;
        acc.w += e0.y * v0.w;
    }

    float s2 = di * di;
    float4 h = *(const float4*)(g_h1 + (size_t)node * F_HID + c * 4);
    float4 b = ((const float4*)b1)[c];
    float4 o;
    o.x = fmaxf(acc.x + s2 * h.x + b.x, 0.0f);
    o.y = fmaxf(acc.y + s2 * h.y + b.y, 0.0f);
    o.z = fmaxf(acc.z + s2 * h.z + b.z, 0.0f);
    o.w = fmaxf(acc.w + s2 * h.w + b.w, 0.0f);
    *(float4*)(g_agg1 + (size_t)node * F_HID + c * 4) = o;
}

// ---------------------------------------------------------------------------
// GEMM2: g_h2[N,40] = g_agg1[N,64] @ W2[64,40]   (FFMA2, R6 config)
// ---------------------------------------------------------------------------
#define G2_ROWS 128

__global__ void k_gemm2(const float* __restrict__ W2) {
    __shared__ float rs[F_HID][G2_ROWS];   // 32 KB, k-major
    __shared__ float ws2[F_HID][F_OUT];    // 10 KB

    int t    = threadIdx.x;
    int row0 = blockIdx.x * G2_ROWS;
    int tx   = t & 7;         // cols tx*5 .. +4
    int ty   = t >> 3;        // rows ty*4 .. +3

    #pragma unroll
    for (int j = 0; j < 3; j++) {
        int i = t + j * 256;
        if (i < 640) ((float4*)ws2)[i] = ((const float4*)W2)[i];
    }
    #pragma unroll
    for (int j = 0; j < 8; j++) {
        int idx = t + j * 256;
        int r   = idx & 127;
        int kq  = idx >> 7;
        int gr  = row0 + r;
        if (gr >= N_NODES) gr = N_NODES - 1;
        float4 v = *(const float4*)(g_agg1 + (size_t)gr * F_HID + kq * 4);
        rs[kq * 4 + 0][r] = v.x;
        rs[kq * 4 + 1][r] = v.y;
        rs[kq * 4 + 2][r] = v.z;
        rs[kq * 4 + 3][r] = v.w;
    }
    __syncthreads();

    unsigned long long acc2[2][5];
    #pragma unroll
    for (int p = 0; p < 2; p++)
        #pragma unroll
        for (int j = 0; j < 5; j++) acc2[p][j] = f2pack(0.0f, 0.0f);

    #pragma unroll
    for (int kk = 0; kk < F_HID; kk++) {
        unsigned long long ap0, ap1;
        lds_v2u64(ap0, ap1, &rs[kk][ty * 4]);
        const float* wrow = &ws2[kk][tx * 5];
        #pragma unroll
        for (int j = 0; j < 5; j++) {
            float bj = wrow[j];
            unsigned long long bd = f2pack(bj, bj);
            fma2(acc2[0][j], ap0, bd);
            fma2(acc2[1][j], ap1, bd);
        }
    }

    #pragma unroll
    for (int p = 0; p < 2; p++) {
        float lo[5], hi[5];
        #pragma unroll
        for (int j = 0; j < 5; j++) f2unpack(acc2[p][j], lo[j], hi[j]);
        int gr0 = row0 + ty * 4 + 2 * p;
        if (gr0 < N_NODES) {
            float* o = g_h2 + (size_t)gr0 * F_OUT + tx * 5;
            #pragma unroll
            for (int j = 0; j < 5; j++) o[j] = lo[j];
        }
        if (gr0 + 1 < N_NODES) {
            float* o = g_h2 + (size_t)(gr0 + 1) * F_OUT + tx * 5;
            #pragma unroll
            for (int j = 0; j < 5; j++) o[j] = hi[j];
        }
    }
}

// ---------------------------------------------------------------------------
// Layer-2 CSR aggregation: 10 threads/node (all active), fuses b2 + self-loop.
// ---------------------------------------------------------------------------
__global__ void k_agg2_csr(const float* __restrict__ b2,
                           float* __restrict__ out) {
    int idx  = blockIdx.x * blockDim.x + threadIdx.x;
    int node = idx / 10;
    int c    = idx - node * 10;
    if (node >= N_NODES) return;
    int beg = g_rowptr[node];
    int cnt = g_cnt[node];
    float di = g_dis[node];

    float4 acc = make_float4(0.f, 0.f, 0.f, 0.f);
    int j = 0;
    for (; j + 1 < cnt; j += 2) {
        float2 e0 = g_edge[beg + j];
        float2 e1 = g_edge[beg + j + 1];
        int s0 = __float_as_int(e0.x);
        int s1 = __float_as_int(e1.x);
        float4 v0 = *(const float4*)(g_h2 + (size_t)s0 * F_OUT + c * 4);
        float4 v1 = *(const float4*)(g_h2 + (size_t)s1 * F_OUT + c * 4);
        acc.x += e0.y * v0.x + e1.y * v1.x;
        acc.y += e0.y * v0.y + e1.y * v1.y;
        acc.z += e0.y * v0.z + e1.y * v1.z;
        acc.w += e0.y * v0.w + e1.y * v1.w;
    }
    if (j < cnt) {
        float2 e0 = g_edge[beg + j];
        int s0 = __float_as_int(e0.x);
        float4 v0 = *(const float4*)(g_h2 + (size_t)s0 * F_OUT + c * 4);
        acc.x += e0.y * v0.x;
        acc.y += e0.y * v0.y;
        acc.z += e0.y * v0.z;
        acc.w += e0.y * v0.w;
    }

    float s2 = di * di;
    float4 h = *(const float4*)(g_h2 + (size_t)node * F_OUT + c * 4);
    float4 b = ((const float4*)b2)[c];
    float4 o;
    o.x = acc.x + s2 * h.x + b.x;
    o.y = acc.y + s2 * h.y + b.y;
    o.z = acc.z + s2 * h.z + b.z;
    o.w = acc.w + s2 * h.w + b.w;
    *(float4*)(out + (size_t)node * F_OUT + c * 4) = o;
}

// ---------------------------------------------------------------------------
extern "C" void kernel_launch(void* const* d_in, const int* in_sizes, int n_in,
                              void* d_out, int out_size) {
    const float* x  = (const float*)d_in[0];
    const int*   ei = (const int*)d_in[1];
    const float* ew = (const float*)d_in[2];
    const float* W1 = (const float*)d_in[3];
    const float* b1 = (const float*)d_in[4];
    const float* W2 = (const float*)d_in[5];
    const float* b2 = (const float*)d_in[6];
    float* out = (float*)d_out;

    int N = in_sizes[0] / F_IN;     // 100000
    int E = in_sizes[2];            // 1600000
    int nblk = (N + 255) / 256;     // 391

    // CSR build + normalization + W split
    k_zero_cd<<<nblk, 256>>>(N);
    k_splitW1<<<(F_IN * F_HID + 255) / 256, 256>>>(W1);
    k_count<<<(E + 255) / 256, 256>>>(ei, ew, E);
    k_scan_local<<<nblk, 256>>>(N);
    k_scan_add<<<nblk, 256>>>(N);      // fused bsum-reduce + rowptr + dis
    k_fill<<<(E + 255) / 256, 256>>>(ei, ew, E);

    // layer 1
    k_gemm1<<<(N + G1_ROWS - 1) / G1_ROWS, 256>>>(x);
    {
        long long items = (long long)N * 16;
        k_agg1_csr<<<(int)((items + 255) / 256), 256>>>(b1);
    }

    // layer 2
    k_gemm2<<<(N + G2_ROWS - 1) / G2_ROWS, 256>>>(W2);
    {
        long long items = (long long)N * 10;
        k_agg2_csr<<<(int)((items + 255) / 256), 256>>>(b2, out);
    }
}